// round 10
// baseline (speedup 1.0000x reference)
#include <cuda_runtime.h>
#include <cuda_bf16.h>
#include <cstddef>

// Problem constants: N=100000, E=1000000, F=64, H=8, D=8
#define MAXN 100000
#define MAXE 1000000
#define CLIPV 5.0f
#define INV_SQRT_D 0.35355339059327373f
#define STR 68     // padded smem row stride (floats)
#define TROWS 128  // proj tile rows
#define PT 8       // proj tiles per block

// ---------------- scratch (device globals) -----------------------------------
__device__ float g_Q[(size_t)MAXN * 64];
__device__ float g_K[(size_t)MAXN * 64];
__device__ float g_V[(size_t)MAXN * 64];
__device__ float g_acc[(size_t)MAXN * 72];  // 64 wV + 8 z per node
__device__ float g_sc[(size_t)MAXE * 8];    // per (edge,head) clipped score
__device__ float g_w[(size_t)MAXE * 8];     // per (edge,head) exp weight

// ---------------- helpers ----------------------------------------------------
__device__ __forceinline__ float clipf(float x) {
    return fminf(fmaxf(x, -CLIPV), CLIPV);
}
__device__ __forceinline__ void red4(float* p, float a, float b, float c, float d) {
    asm volatile("red.global.add.v4.f32 [%0], {%1, %2, %3, %4};"
                 :: "l"(p), "f"(a), "f"(b), "f"(c), "f"(d) : "memory");
}
__device__ __forceinline__ void red1(float* p, float v) {
    asm volatile("red.global.add.f32 [%0], %1;" :: "l"(p), "f"(v) : "memory");
}
__device__ __forceinline__ void split2(float x0, float x1, unsigned& hi, unsigned& lo) {
    __nv_bfloat16 h0 = __float2bfloat16_rn(x0);
    __nv_bfloat16 h1 = __float2bfloat16_rn(x1);
    float r0 = x0 - __bfloat162float(h0);
    float r1 = x1 - __bfloat162float(h1);
    __nv_bfloat162 H; H.x = h0; H.y = h1;
    __nv_bfloat162 L; L.x = __float2bfloat16_rn(r0); L.y = __float2bfloat16_rn(r1);
    hi = *reinterpret_cast<unsigned*>(&H);
    lo = *reinterpret_cast<unsigned*>(&L);
}
__device__ __forceinline__ void mma_bf16(float c[4], const unsigned a[4], const unsigned b[2]) {
    asm volatile(
        "mma.sync.aligned.m16n8k16.row.col.f32.bf16.bf16.f32 "
        "{%0,%1,%2,%3}, {%4,%5,%6,%7}, {%8,%9}, {%0,%1,%2,%3};"
        : "+f"(c[0]), "+f"(c[1]), "+f"(c[2]), "+f"(c[3])
        : "r"(a[0]), "r"(a[1]), "r"(a[2]), "r"(a[3]), "r"(b[0]), "r"(b[1]));
}
__device__ __forceinline__ void load_a_frags(const float* sT, int R, int lq, int lr,
                                             unsigned ah[4][4], unsigned al[4][4]) {
    #pragma unroll
    for (int k = 0; k < 4; k++) {
        const float* base = sT + (size_t)(R + lq) * STR + 16 * k + 2 * lr;
        float2 q0 = *reinterpret_cast<const float2*>(base);
        float2 q1 = *reinterpret_cast<const float2*>(base + 8 * STR);
        float2 q2 = *reinterpret_cast<const float2*>(base + 8);
        float2 q3 = *reinterpret_cast<const float2*>(base + 8 * STR + 8);
        split2(q0.x, q0.y, ah[k][0], al[k][0]);
        split2(q1.x, q1.y, ah[k][1], al[k][1]);
        split2(q2.x, q2.y, ah[k][2], al[k][2]);
        split2(q3.x, q3.y, ah[k][3], al[k][3]);
    }
}
__device__ __forceinline__ unsigned saddr(const void* p) {
    return (unsigned)__cvta_generic_to_shared(p);
}

// ---------------- kernel 1: node projections Q,K,V (tensor-core) + acc zero --
__global__ __launch_bounds__(256)
void node_mma_kernel(const float* __restrict__ nf,
                     const float* __restrict__ Wq, const float* __restrict__ bq,
                     const float* __restrict__ Wk, const float* __restrict__ bk,
                     const float* __restrict__ Wv, const float* __restrict__ bv,
                     int N) {
    extern __shared__ float smem[];
    float* sX = smem;               // [128][STR]
    float* sW = smem + 128 * STR;   // [192][STR]

    int tid = threadIdx.x;
    long nBase = (long)blockIdx.x * 128;

    {
        float4 z4 = make_float4(0.f, 0.f, 0.f, 0.f);
        float4* ap = reinterpret_cast<float4*>(g_acc);
        long total4 = (long)N * 18;
        for (long i = (long)blockIdx.x * 256 + tid; i < total4; i += (long)gridDim.x * 256)
            ap[i] = z4;
    }

    for (int i = tid; i < 4096; i += 256) {
        int r = i >> 6, c = i & 63;
        sW[(size_t)r * STR + c]         = Wq[i];
        sW[(size_t)(64 + r) * STR + c]  = Wk[i];
        sW[(size_t)(128 + r) * STR + c] = Wv[i];
    }
    for (int i = tid; i < 128 * 16; i += 256) {
        int r = i >> 4, c4 = i & 15;
        long nn = nBase + r;
        float4 v = make_float4(0.f, 0.f, 0.f, 0.f);
        if (nn < N) v = *reinterpret_cast<const float4*>(nf + nn * 64 + c4 * 4);
        *reinterpret_cast<float4*>(sX + (size_t)r * STR + c4 * 4) = v;
    }
    __syncthreads();

    int w = tid >> 5, l = tid & 31;
    int lq = l >> 2, lr = l & 3;

    unsigned bh[3][4][2], bl[3][4][2];
    #pragma unroll
    for (int t = 0; t < 3; t++) {
        int n = 8 * (3 * w + t) + lq;
        #pragma unroll
        for (int k = 0; k < 4; k++) {
            float2 p0 = *reinterpret_cast<const float2*>(sW + (size_t)n * STR + 16 * k + 2 * lr);
            float2 p1 = *reinterpret_cast<const float2*>(sW + (size_t)n * STR + 16 * k + 2 * lr + 8);
            split2(p0.x, p0.y, bh[t][k][0], bl[t][k][0]);
            split2(p1.x, p1.y, bh[t][k][1], bl[t][k][1]);
        }
    }

    #pragma unroll 1
    for (int mt = 0; mt < 8; mt++) {
        int R = 16 * mt;
        unsigned ah[4][4], al[4][4];
        load_a_frags(sX, R, lq, lr, ah, al);

        #pragma unroll
        for (int t = 0; t < 3; t++) {
            float acc[4] = {0.f, 0.f, 0.f, 0.f};
            #pragma unroll
            for (int k = 0; k < 4; k++) {
                mma_bf16(acc, ah[k], bh[t][k]);
                mma_bf16(acc, ah[k], bl[t][k]);
                mma_bf16(acc, al[k], bh[t][k]);
            }
            int g = 3 * w + t;
            int which = g >> 3;
            int colBase = 8 * (g & 7) + 2 * lr;
            float* outp = (which == 0) ? g_Q : (which == 1) ? g_K : g_V;
            const float* bp = (which == 0) ? bq : (which == 1) ? bk : bv;
            float2 bb = __ldg(reinterpret_cast<const float2*>(bp + colBase));
            long n0 = nBase + R + lq;
            long n1 = n0 + 8;
            if (n0 < N)
                *reinterpret_cast<float2*>(outp + n0 * 64 + colBase) =
                    make_float2(acc[0] + bb.x, acc[1] + bb.y);
            if (n1 < N)
                *reinterpret_cast<float2*>(outp + n1 * 64 + colBase) =
                    make_float2(acc[2] + bb.x, acc[3] + bb.y);
        }
    }
}

// ---------------- kernel 2: scores sc[e][h] = clip(K[src].Q[dst]/sqrt(D)) ----
__global__ __launch_bounds__(256)
void score_kernel(const int* __restrict__ src, const int* __restrict__ dst,
                  long eOff, int E) {
    long t = (long)blockIdx.x * 256 + threadIdx.x;
    long e = eOff + (t >> 3);
    if (e >= E) return;
    int h = (int)(t & 7);

    int s = __ldg(src + e);
    int d = __ldg(dst + e);

    const float4* Kp = reinterpret_cast<const float4*>(g_K + (size_t)s * 64 + 8 * h);
    const float4* Qp = reinterpret_cast<const float4*>(g_Q + (size_t)d * 64 + 8 * h);
    float4 k0 = Kp[0], k1 = Kp[1];
    float4 q0 = Qp[0], q1 = Qp[1];

    float sc = k0.x * q0.x + k0.y * q0.y + k0.z * q0.z + k0.w * q0.w
             + k1.x * q1.x + k1.y * q1.y + k1.z * q1.z + k1.w * q1.w;
    g_sc[e * 8 + h] = clipf(sc * INV_SQRT_D);   // coalesced
}

// ---------------- kernel 3: pipelined edge projection GEMM -------------------
// 128-row tiles, PT per block, cp.async double buffer (ef) + triple buffer (sc).
// Warp = (m-pair, n-half); B fragments register-resident for the whole kernel
// (loaded once from global -> zero per-tile smem B traffic).
__global__ __launch_bounds__(256, 2)
void edge_proj_kernel(const float* __restrict__ ef,
                      const float* __restrict__ We, const float* __restrict__ be,
                      float* __restrict__ e_out, int E) {
    extern __shared__ float smem[];
    float* bufs[2] = { smem, smem + TROWS * STR };
    float* sScs[3] = { smem + 2 * TROWS * STR,
                       smem + 2 * TROWS * STR + 1024,
                       smem + 2 * TROWS * STR + 2048 };   // [128][8] each

    int tid = threadIdx.x;
    long base = (long)blockIdx.x * (TROWS * PT);

    int w = tid >> 5, l = tid & 31;
    int lq = l >> 2, lr = l & 3;
    int mpair = w & 3;      // m-tiles 2*mpair, 2*mpair+1 (rows 32*mpair..+31)
    int nh = w >> 2;        // n-half: heads 4*nh..4*nh+3
    int R1 = 32 * mpair;
    int R2 = R1 + 16;

    // B fragments: register-resident for all PT tiles (64 regs)
    unsigned bh[4][4][2], bl[4][4][2];
    #pragma unroll
    for (int tt = 0; tt < 4; tt++) {
        int n = 8 * (4 * nh + tt) + lq;
        #pragma unroll
        for (int k = 0; k < 4; k++) {
            const float* wr = We + (size_t)n * 64 + 16 * k + 2 * lr;
            float2 a = __ldg(reinterpret_cast<const float2*>(wr));
            float2 b = __ldg(reinterpret_cast<const float2*>(wr + 8));
            split2(a.x, a.y, bh[tt][k][0], bl[tt][k][0]);
            split2(b.x, b.y, bh[tt][k][1], bl[tt][k][1]);
        }
    }
    // bias fragments for my 4 heads
    float2 bb[4];
    #pragma unroll
    for (int tt = 0; tt < 4; tt++)
        bb[tt] = __ldg(reinterpret_cast<const float2*>(be + 8 * (4 * nh + tt) + 2 * lr));

    // async tile loader: ef rows (clamped) + this tile's scores
    auto load_tile = [&](int tileIdx) {
        float* buf = bufs[tileIdx & 1];
        long tBase = base + (long)tileIdx * TROWS;
        #pragma unroll
        for (int it = 0; it < 8; it++) {
            int i = it * 256 + tid;
            int r = i >> 4, c4 = i & 15;
            long e = tBase + r;
            if (e >= E) e = E - 1;
            const float* srcp = ef + e * 64 + 4 * c4;
            unsigned daddr = saddr(buf + (size_t)r * STR + 4 * c4);
            asm volatile("cp.async.cg.shared.global [%0], [%1], 16;"
                         :: "r"(daddr), "l"(srcp));
        }
        {   // scores: 4KB contiguous, one 16B op per thread (clamped)
            long off = tBase * 8 + (long)tid * 4;
            long lim = (long)E * 8 - 4;
            if (off > lim) off = lim;
            unsigned daddr = saddr(sScs[tileIdx % 3] + tid * 4);
            asm volatile("cp.async.cg.shared.global [%0], [%1], 16;"
                         :: "r"(daddr), "l"(g_sc + off));
        }
        asm volatile("cp.async.commit_group;");
    };

    load_tile(0);
    load_tile(1);

    #pragma unroll 1
    for (int t = 0; t < PT; t++) {
        float* buf = bufs[t & 1];
        float* sSc = sScs[t % 3];
        long tBase = base + (long)t * TROWS;

        if (t == PT - 1) asm volatile("cp.async.wait_group 0;");
        else             asm volatile("cp.async.wait_group 1;");
        __syncthreads();   // tile t data + scores visible

        // ---- m-tile 1 ----
        unsigned ah[4][4], al[4][4];
        load_a_frags(buf, R1, lq, lr, ah, al);
        {
            long e0 = tBase + R1 + lq;
            long e1 = e0 + 8;
            #pragma unroll
            for (int tt = 0; tt < 4; tt++) {
                int tn = 4 * nh + tt;
                float acc[4] = {0.f, 0.f, 0.f, 0.f};
                #pragma unroll
                for (int k = 0; k < 4; k++) {
                    mma_bf16(acc, ah[k], bh[tt][k]);
                    mma_bf16(acc, ah[k], bl[tt][k]);
                    mma_bf16(acc, al[k], bh[tt][k]);
                }
                float p0 = acc[0] + bb[tt].x, p1 = acc[1] + bb[tt].y;
                float p2 = acc[2] + bb[tt].x, p3 = acc[3] + bb[tt].y;
                float ps0 = p0 + p1, ps1 = p2 + p3;
                ps0 += __shfl_xor_sync(0xffffffffu, ps0, 1);
                ps0 += __shfl_xor_sync(0xffffffffu, ps0, 2);
                ps1 += __shfl_xor_sync(0xffffffffu, ps1, 1);
                ps1 += __shfl_xor_sync(0xffffffffu, ps1, 2);
                float sc0 = sSc[(R1 + lq) * 8 + tn];
                float sc1 = sSc[(R1 + 8 + lq) * 8 + tn];
                int colBase = 8 * tn + 2 * lr;
                if (e0 < E) {
                    __stcs(reinterpret_cast<float2*>(e_out + e0 * 64 + colBase),
                           make_float2(sc0 * p0, sc0 * p1));
                    if (lr == 0) g_w[e0 * 8 + tn] = __expf(clipf(sc0 * ps0));
                }
                if (e1 < E) {
                    __stcs(reinterpret_cast<float2*>(e_out + e1 * 64 + colBase),
                           make_float2(sc1 * p2, sc1 * p3));
                    if (lr == 0) g_w[e1 * 8 + tn] = __expf(clipf(sc1 * ps1));
                }
            }
        }

        // ---- m-tile 2: A load, then free the buffer for t+2 ----
        load_a_frags(buf, R2, lq, lr, ah, al);
        __syncthreads();   // all warps done reading buf (sc buffer differs mod 3)
        if (t + 2 < PT) load_tile(t + 2);   // overlaps second MMA burst

        {
            long e0 = tBase + R2 + lq;
            long e1 = e0 + 8;
            #pragma unroll
            for (int tt = 0; tt < 4; tt++) {
                int tn = 4 * nh + tt;
                float acc[4] = {0.f, 0.f, 0.f, 0.f};
                #pragma unroll
                for (int k = 0; k < 4; k++) {
                    mma_bf16(acc, ah[k], bh[tt][k]);
                    mma_bf16(acc, ah[k], bl[tt][k]);
                    mma_bf16(acc, al[k], bh[tt][k]);
                }
                float p0 = acc[0] + bb[tt].x, p1 = acc[1] + bb[tt].y;
                float p2 = acc[2] + bb[tt].x, p3 = acc[3] + bb[tt].y;
                float ps0 = p0 + p1, ps1 = p2 + p3;
                ps0 += __shfl_xor_sync(0xffffffffu, ps0, 1);
                ps0 += __shfl_xor_sync(0xffffffffu, ps0, 2);
                ps1 += __shfl_xor_sync(0xffffffffu, ps1, 1);
                ps1 += __shfl_xor_sync(0xffffffffu, ps1, 2);
                float sc0 = sSc[(R2 + lq) * 8 + tn];
                float sc1 = sSc[(R2 + 8 + lq) * 8 + tn];
                int colBase = 8 * tn + 2 * lr;
                if (e0 < E) {
                    __stcs(reinterpret_cast<float2*>(e_out + e0 * 64 + colBase),
                           make_float2(sc0 * p0, sc0 * p1));
                    if (lr == 0) g_w[e0 * 8 + tn] = __expf(clipf(sc0 * ps0));
                }
                if (e1 < E) {
                    __stcs(reinterpret_cast<float2*>(e_out + e1 * 64 + colBase),
                           make_float2(sc1 * p2, sc1 * p3));
                    if (lr == 0) g_w[e1 * 8 + tn] = __expf(clipf(sc1 * ps1));
                }
            }
        }
    }
}

// ---------------- kernel 4: scatter wV and z into g_acc ----------------------
__global__ __launch_bounds__(256)
void scatter_kernel(const int* __restrict__ src, const int* __restrict__ dst,
                    int E) {
    long t = (long)blockIdx.x * 256 + threadIdx.x;
    long e = t >> 3;
    if (e >= E) return;
    int h = (int)(t & 7);

    int s = __ldg(src + e);
    int d = __ldg(dst + e);
    float wv = __ldg(g_w + t);   // coalesced

    const float4* Vp = reinterpret_cast<const float4*>(g_V + (size_t)s * 64 + 8 * h);
    float4 v0 = Vp[0], v1 = Vp[1];

    float* ap = g_acc + (size_t)d * 72 + 8 * h;
    red4(ap,     v0.x * wv, v0.y * wv, v0.z * wv, v0.w * wv);
    red4(ap + 4, v1.x * wv, v1.y * wv, v1.z * wv, v1.w * wv);
    red1(g_acc + (size_t)d * 72 + 64 + h, wv);
}

// ---------------- kernel 5: finalize h_out = wV / (z + 1e-6) -----------------
__global__ __launch_bounds__(256)
void finalize_kernel(float* __restrict__ h_out, int N) {
    int t = blockIdx.x * 256 + threadIdx.x;
    if (t >= N * 16) return;
    int n = t >> 4, g = t & 15;
    const float* ap = g_acc + (size_t)n * 72;
    float4 wv = *reinterpret_cast<const float4*>(ap + 4 * g);
    float z = ap[64 + (g >> 1)];
    float inv = 1.0f / (z + 1e-6f);
    float4 r;
    r.x = wv.x * inv; r.y = wv.y * inv; r.z = wv.z * inv; r.w = wv.w * inv;
    __stcs(reinterpret_cast<float4*>(h_out + (size_t)n * 64 + 4 * g), r);
}

// ---------------- launch ------------------------------------------------------
extern "C" void kernel_launch(void* const* d_in, const int* in_sizes, int n_in,
                              void* d_out, int out_size) {
    const float* nf = (const float*)d_in[0];
    const float* ef = (const float*)d_in[1];
    const int*   src = (const int*)d_in[2];
    const int*   dst = (const int*)d_in[3];
    const float* Wq = (const float*)d_in[4];
    const float* bq = (const float*)d_in[5];
    const float* Wk = (const float*)d_in[6];
    const float* bk = (const float*)d_in[7];
    const float* Wv = (const float*)d_in[8];
    const float* bv = (const float*)d_in[9];
    const float* We = (const float*)d_in[10];
    const float* be = (const float*)d_in[11];

    int N = in_sizes[0] / 64;
    int E = in_sizes[2];

    float* h_out = (float*)d_out;                  // [N, 64]
    float* e_out = (float*)d_out + (size_t)N * 64; // [E, 64]

    const int NODE_SMEM = (128 + 192) * STR * 4;                   // 87040
    const int PROJ_SMEM = 2 * TROWS * STR * 4 + 3 * 4096;          // 69632+12288=81920
    cudaFuncSetAttribute(node_mma_kernel,
                         cudaFuncAttributeMaxDynamicSharedMemorySize, NODE_SMEM);
    cudaFuncSetAttribute(edge_proj_kernel,
                         cudaFuncAttributeMaxDynamicSharedMemorySize, PROJ_SMEM);

    // launch order: node(0), score_a(1), score_b(2), proj(3), scatter(4), fin(5)
    // -> ncu capture (absolute launch index 3) lands on edge_proj_kernel
    node_mma_kernel<<<(N + 127) / 128, 256, NODE_SMEM>>>(nf, Wq, bq, Wk, bk, Wv, bv, N);

    long half = (E + 1) / 2;
    {
        int blocks = (int)((half * 8 + 255) / 256);
        score_kernel<<<blocks, 256>>>(src, dst, 0, (int)half);
    }
    {
        long cnt = E - half;
        int blocks = (int)((cnt * 8 + 255) / 256);
        score_kernel<<<blocks, 256>>>(src, dst, half, E);
    }

    {
        int blocks = (int)((E + TROWS * PT - 1) / (TROWS * PT));
        edge_proj_kernel<<<blocks, 256, PROJ_SMEM>>>(ef, We, be, e_out, E);
    }

    int sblocks = (int)(((long)E * 8 + 255) / 256);
    scatter_kernel<<<sblocks, 256>>>(src, dst, E);

    finalize_kernel<<<((N * 16) + 255) / 256, 256>>>(h_out, N);
}

// round 11
// speedup vs baseline: 1.1866x; 1.1866x over previous
#include <cuda_runtime.h>
#include <cuda_bf16.h>
#include <cstddef>

// Problem constants: N=100000, E=1000000, F=64, H=8, D=8
#define MAXN 100000
#define MAXE 1000000
#define CLIPV 5.0f
#define INV_SQRT_D 0.35355339059327373f
#define STR 68      // padded smem row stride (floats)
#define NTROWS 64   // node tile rows
#define NPT 4       // node tiles per block
#define ETROWS 64   // proj tile rows
#define EPT 8       // proj tiles per block

// ---------------- scratch (device globals) -----------------------------------
__device__ float g_Q[(size_t)MAXN * 64];
__device__ float g_K[(size_t)MAXN * 64];
__device__ float g_V[(size_t)MAXN * 64];
__device__ float g_acc[(size_t)MAXN * 72];  // 64 wV + 8 z per node
__device__ float g_sc[(size_t)MAXE * 8];    // per (edge,head) clipped score
__device__ float g_w[(size_t)MAXE * 8];     // per (edge,head) exp weight

// ---------------- helpers ----------------------------------------------------
__device__ __forceinline__ float clipf(float x) {
    return fminf(fmaxf(x, -CLIPV), CLIPV);
}
__device__ __forceinline__ void red4(float* p, float a, float b, float c, float d) {
    asm volatile("red.global.add.v4.f32 [%0], {%1, %2, %3, %4};"
                 :: "l"(p), "f"(a), "f"(b), "f"(c), "f"(d) : "memory");
}
__device__ __forceinline__ void split2(float x0, float x1, unsigned& hi, unsigned& lo) {
    __nv_bfloat16 h0 = __float2bfloat16_rn(x0);
    __nv_bfloat16 h1 = __float2bfloat16_rn(x1);
    float r0 = x0 - __bfloat162float(h0);
    float r1 = x1 - __bfloat162float(h1);
    __nv_bfloat162 H; H.x = h0; H.y = h1;
    __nv_bfloat162 L; L.x = __float2bfloat16_rn(r0); L.y = __float2bfloat16_rn(r1);
    hi = *reinterpret_cast<unsigned*>(&H);
    lo = *reinterpret_cast<unsigned*>(&L);
}
__device__ __forceinline__ void mma_bf16(float c[4], const unsigned a[4], const unsigned b[2]) {
    asm volatile(
        "mma.sync.aligned.m16n8k16.row.col.f32.bf16.bf16.f32 "
        "{%0,%1,%2,%3}, {%4,%5,%6,%7}, {%8,%9}, {%0,%1,%2,%3};"
        : "+f"(c[0]), "+f"(c[1]), "+f"(c[2]), "+f"(c[3])
        : "r"(a[0]), "r"(a[1]), "r"(a[2]), "r"(a[3]), "r"(b[0]), "r"(b[1]));
}
__device__ __forceinline__ void load_a_frags(const float* sT, int R, int lq, int lr,
                                             unsigned ah[4][4], unsigned al[4][4]) {
    #pragma unroll
    for (int k = 0; k < 4; k++) {
        const float* base = sT + (size_t)(R + lq) * STR + 16 * k + 2 * lr;
        float2 q0 = *reinterpret_cast<const float2*>(base);
        float2 q1 = *reinterpret_cast<const float2*>(base + 8 * STR);
        float2 q2 = *reinterpret_cast<const float2*>(base + 8);
        float2 q3 = *reinterpret_cast<const float2*>(base + 8 * STR + 8);
        split2(q0.x, q0.y, ah[k][0], al[k][0]);
        split2(q1.x, q1.y, ah[k][1], al[k][1]);
        split2(q2.x, q2.y, ah[k][2], al[k][2]);
        split2(q3.x, q3.y, ah[k][3], al[k][3]);
    }
}
__device__ __forceinline__ unsigned saddr(const void* p) {
    return (unsigned)__cvta_generic_to_shared(p);
}

// ---------------- kernel 0: zero g_acc ---------------------------------------
__global__ __launch_bounds__(256)
void zero_acc_kernel(int N) {
    float4 z4 = make_float4(0.f, 0.f, 0.f, 0.f);
    float4* ap = reinterpret_cast<float4*>(g_acc);
    long total4 = (long)N * 18;
    for (long i = (long)blockIdx.x * 256 + threadIdx.x; i < total4;
         i += (long)gridDim.x * 256)
        ap[i] = z4;
}

// ---------------- kernel 1: node projections (pipelined, B in regs) ----------
// 64-row tiles, NPT per block, cp.async double buffer.
// Warp w owns n-tiles {3w, 3w+1, 3w+2} of 24 (Q:0-7, K:8-15, V:16-23);
// B fragments (48 regs) + bias loaded once from global.
__global__ __launch_bounds__(256, 2)
void node_mma_kernel(const float* __restrict__ nf,
                     const float* __restrict__ Wq, const float* __restrict__ bq,
                     const float* __restrict__ Wk, const float* __restrict__ bk,
                     const float* __restrict__ Wv, const float* __restrict__ bv,
                     long nOff, int N) {
    extern __shared__ float smem[];
    float* bufs[2] = { smem, smem + NTROWS * STR };

    int tid = threadIdx.x;
    long base = nOff + (long)blockIdx.x * (NTROWS * NPT);

    int w = tid >> 5, l = tid & 31;
    int lq = l >> 2, lr = l & 3;

    // B fragments + bias for my 3 n-tiles (register-resident)
    unsigned bh[3][4][2], bl[3][4][2];
    float2 bb[3];
    #pragma unroll
    for (int t3 = 0; t3 < 3; t3++) {
        int g = 3 * w + t3;
        int which = g >> 3;
        const float* W = (which == 0) ? Wq : (which == 1) ? Wk : Wv;
        const float* bp = (which == 0) ? bq : (which == 1) ? bk : bv;
        int nrow = (g & 7) * 8 + lq;
        #pragma unroll
        for (int k = 0; k < 4; k++) {
            const float* wr = W + (size_t)nrow * 64 + 16 * k + 2 * lr;
            float2 a = __ldg(reinterpret_cast<const float2*>(wr));
            float2 b = __ldg(reinterpret_cast<const float2*>(wr + 8));
            split2(a.x, a.y, bh[t3][k][0], bl[t3][k][0]);
            split2(b.x, b.y, bh[t3][k][1], bl[t3][k][1]);
        }
        bb[t3] = __ldg(reinterpret_cast<const float2*>(bp + (g & 7) * 8 + 2 * lr));
    }

    auto load_tile = [&](int ti) {
        float* buf = bufs[ti & 1];
        long tBase = base + (long)ti * NTROWS;
        #pragma unroll
        for (int it = 0; it < 4; it++) {
            int i = it * 256 + tid;
            int r = i >> 4, c4 = i & 15;
            long n = tBase + r;
            if (n >= N) n = N - 1;
            const float* srcp = nf + n * 64 + 4 * c4;
            unsigned daddr = saddr(buf + (size_t)r * STR + 4 * c4);
            asm volatile("cp.async.cg.shared.global [%0], [%1], 16;"
                         :: "r"(daddr), "l"(srcp));
        }
        asm volatile("cp.async.commit_group;");
    };

    load_tile(0);
    load_tile(1);

    #pragma unroll 1
    for (int t = 0; t < NPT; t++) {
        float* buf = bufs[t & 1];
        long tBase = base + (long)t * NTROWS;

        if (t == NPT - 1) asm volatile("cp.async.wait_group 0;");
        else              asm volatile("cp.async.wait_group 1;");
        __syncthreads();

        #pragma unroll
        for (int mt = 0; mt < 4; mt++) {
            unsigned ah[4][4], al[4][4];
            load_a_frags(buf, 16 * mt, lq, lr, ah, al);
            if (mt == 3) {   // all warps done reading buf -> free for t+2
                __syncthreads();
                if (t + 2 < NPT) load_tile(t + 2);
            }
            long n0 = tBase + 16 * mt + lq;
            long n1 = n0 + 8;
            #pragma unroll
            for (int t3 = 0; t3 < 3; t3++) {
                int g = 3 * w + t3;
                int which = g >> 3;
                float* outp = (which == 0) ? g_Q : (which == 1) ? g_K : g_V;
                int colBase = 8 * (g & 7) + 2 * lr;
                float acc[4] = {0.f, 0.f, 0.f, 0.f};
                #pragma unroll
                for (int k = 0; k < 4; k++) {
                    mma_bf16(acc, ah[k], bh[t3][k]);
                    mma_bf16(acc, ah[k], bl[t3][k]);
                    mma_bf16(acc, al[k], bh[t3][k]);
                }
                if (n0 < N)
                    *reinterpret_cast<float2*>(outp + n0 * 64 + colBase) =
                        make_float2(acc[0] + bb[t3].x, acc[1] + bb[t3].y);
                if (n1 < N)
                    *reinterpret_cast<float2*>(outp + n1 * 64 + colBase) =
                        make_float2(acc[2] + bb[t3].x, acc[3] + bb[t3].y);
            }
        }
    }
}

// ---------------- kernel 2: scores sc[e][h] = clip(K[src].Q[dst]/sqrt(D)) ----
__global__ __launch_bounds__(256)
void score_kernel(const int* __restrict__ src, const int* __restrict__ dst,
                  int E) {
    long t = (long)blockIdx.x * 256 + threadIdx.x;
    long e = t >> 3;
    if (e >= E) return;
    int h = (int)(t & 7);

    int s = __ldg(src + e);
    int d = __ldg(dst + e);

    const float4* Kp = reinterpret_cast<const float4*>(g_K + (size_t)s * 64 + 8 * h);
    const float4* Qp = reinterpret_cast<const float4*>(g_Q + (size_t)d * 64 + 8 * h);
    float4 k0 = Kp[0], k1 = Kp[1];
    float4 q0 = Qp[0], q1 = Qp[1];

    float sc = k0.x * q0.x + k0.y * q0.y + k0.z * q0.z + k0.w * q0.w
             + k1.x * q1.x + k1.y * q1.y + k1.z * q1.z + k1.w * q1.w;
    g_sc[t] = clipf(sc * INV_SQRT_D);   // coalesced
}

// ---------------- kernel 3: pipelined edge projection GEMM (round-9 form) ----
// 64-row tiles, EPT per block, cp.async double buffer; B frags pre-split in
// 16KB smem; register-resident epilogue (e_out from accumulators, quad-shfl
// row sums); scores triple... staged per tile via 2KB smem buffer.
__global__ __launch_bounds__(256, 3)
void edge_proj_kernel(const float* __restrict__ ef,
                      const float* __restrict__ We, const float* __restrict__ be,
                      float* __restrict__ e_out, int E) {
    extern __shared__ float smem[];
    float* bufs[2] = { smem, smem + ETROWS * STR };
    uint4* sB = reinterpret_cast<uint4*>(smem + 2 * ETROWS * STR);  // [8][4][32] 16KB
    float* sSc = reinterpret_cast<float*>(sB + 1024);               // [64][8] 2KB

    int tid = threadIdx.x;
    long base = (long)blockIdx.x * (ETROWS * EPT);

    for (int i = tid; i < 1024; i += 256) {
        int t = i >> 7, k = (i >> 5) & 3, l = i & 31;
        int lq = l >> 2, lr = l & 3;
        const float* wr = We + (size_t)(8 * t + lq) * 64 + 16 * k + 2 * lr;
        float w0 = __ldg(wr),     w1 = __ldg(wr + 1);
        float w8 = __ldg(wr + 8), w9 = __ldg(wr + 9);
        unsigned h0, l0, h1, l1;
        split2(w0, w1, h0, l0);
        split2(w8, w9, h1, l1);
        sB[i] = make_uint4(h0, h1, l0, l1);
    }

    auto load_tile = [&](float* buf, long tBase) {
        for (int i = tid; i < ETROWS * 16; i += 256) {
            int r = i >> 4, c4 = i & 15;
            long e = tBase + r;
            if (e >= E) e = E - 1;
            const float* srcp = ef + e * 64 + 4 * c4;
            unsigned daddr = saddr(buf + (size_t)r * STR + 4 * c4);
            asm volatile("cp.async.cg.shared.global [%0], [%1], 16;"
                         :: "r"(daddr), "l"(srcp));
        }
        asm volatile("cp.async.commit_group;");
    };

    load_tile(bufs[0], base);
    load_tile(bufs[1], base + ETROWS);

    int w = tid >> 5, l = tid & 31;
    int lq = l >> 2, lr = l & 3;
    int mt = w >> 1;        // m-tile 0..3
    int nh = w & 1;         // n-half: heads 4*nh..4*nh+3
    int R = 16 * mt;

    float2 bb[4];
    #pragma unroll
    for (int tt = 0; tt < 4; tt++)
        bb[tt] = __ldg(reinterpret_cast<const float2*>(be + 8 * (4 * nh + tt) + 2 * lr));

    #pragma unroll 1
    for (int t = 0; t < EPT; t++) {
        float* buf = bufs[t & 1];
        long tBase = base + (long)t * ETROWS;

        if (t == EPT - 1) asm volatile("cp.async.wait_group 0;");
        else              asm volatile("cp.async.wait_group 1;");
        __syncthreads();

        if (tid < 128) {
            long e4 = tBase + (tid >> 1);
            if (e4 < E)
                reinterpret_cast<float4*>(sSc)[tid] =
                    __ldg(reinterpret_cast<const float4*>(g_sc) + tBase * 2 + tid);
        }

        unsigned ah[4][4], al[4][4];
        load_a_frags(buf, R, lq, lr, ah, al);
        __syncthreads();

        if (t + 2 < EPT) load_tile(buf, tBase + 2 * ETROWS);

        long e0 = tBase + R + lq;
        long e1 = e0 + 8;

        #pragma unroll
        for (int tt = 0; tt < 4; tt++) {
            int tn = 4 * nh + tt;
            float acc[4] = {0.f, 0.f, 0.f, 0.f};
            #pragma unroll
            for (int k = 0; k < 4; k++) {
                uint4 b = sB[(tn * 4 + k) * 32 + l];
                unsigned bhv[2] = { b.x, b.y };
                unsigned blv[2] = { b.z, b.w };
                mma_bf16(acc, ah[k], bhv);
                mma_bf16(acc, ah[k], blv);
                mma_bf16(acc, al[k], bhv);
            }
            float p0 = acc[0] + bb[tt].x, p1 = acc[1] + bb[tt].y;
            float p2 = acc[2] + bb[tt].x, p3 = acc[3] + bb[tt].y;
            float ps0 = p0 + p1, ps1 = p2 + p3;
            ps0 += __shfl_xor_sync(0xffffffffu, ps0, 1);
            ps0 += __shfl_xor_sync(0xffffffffu, ps0, 2);
            ps1 += __shfl_xor_sync(0xffffffffu, ps1, 1);
            ps1 += __shfl_xor_sync(0xffffffffu, ps1, 2);
            float sc0 = sSc[(R + lq) * 8 + tn];
            float sc1 = sSc[(R + 8 + lq) * 8 + tn];
            int colBase = 8 * tn + 2 * lr;
            if (e0 < E) {
                __stcs(reinterpret_cast<float2*>(e_out + e0 * 64 + colBase),
                       make_float2(sc0 * p0, sc0 * p1));
                if (lr == 0) g_w[e0 * 8 + tn] = __expf(clipf(sc0 * ps0));
            }
            if (e1 < E) {
                __stcs(reinterpret_cast<float2*>(e_out + e1 * 64 + colBase),
                       make_float2(sc1 * p2, sc1 * p3));
                if (lr == 0) g_w[e1 * 8 + tn] = __expf(clipf(sc1 * ps1));
            }
        }
    }
}

// ---------------- kernel 4: scatter wV and z into g_acc ----------------------
// z adds aggregated: 3 shfls + red4 from lanes h=0,4 (replaces 8 red1/edge).
__global__ __launch_bounds__(256)
void scatter_kernel(const int* __restrict__ src, const int* __restrict__ dst,
                    int E) {
    long t = (long)blockIdx.x * 256 + threadIdx.x;
    long e = t >> 3;
    int h = (int)(t & 7);
    bool valid = e < E;
    long ec = valid ? e : (long)E - 1;

    int s = __ldg(src + ec);
    int d = __ldg(dst + ec);
    float wv = __ldg(g_w + ec * 8 + h);   // coalesced

    const float4* Vp = reinterpret_cast<const float4*>(g_V + (size_t)s * 64 + 8 * h);
    float4 v0 = Vp[0], v1 = Vp[1];

    // aggregate z within each 4-lane run (edge groups are lane-aligned)
    float w1 = __shfl_down_sync(0xffffffffu, wv, 1);
    float w2 = __shfl_down_sync(0xffffffffu, wv, 2);
    float w3 = __shfl_down_sync(0xffffffffu, wv, 3);

    if (valid) {
        float* ap = g_acc + (size_t)d * 72 + 8 * h;
        red4(ap,     v0.x * wv, v0.y * wv, v0.z * wv, v0.w * wv);
        red4(ap + 4, v1.x * wv, v1.y * wv, v1.z * wv, v1.w * wv);
        if ((h & 3) == 0)
            red4(g_acc + (size_t)d * 72 + 64 + h, wv, w1, w2, w3);
    }
}

// ---------------- kernel 5: finalize h_out = wV / (z + 1e-6) -----------------
__global__ __launch_bounds__(256)
void finalize_kernel(float* __restrict__ h_out, int N) {
    int t = blockIdx.x * 256 + threadIdx.x;
    if (t >= N * 16) return;
    int n = t >> 4, g = t & 15;
    const float* ap = g_acc + (size_t)n * 72;
    float4 wv = *reinterpret_cast<const float4*>(ap + 4 * g);
    float z = ap[64 + (g >> 1)];
    float inv = 1.0f / (z + 1e-6f);
    float4 r;
    r.x = wv.x * inv; r.y = wv.y * inv; r.z = wv.z * inv; r.w = wv.w * inv;
    __stcs(reinterpret_cast<float4*>(h_out + (size_t)n * 64 + 4 * g), r);
}

// ---------------- launch ------------------------------------------------------
extern "C" void kernel_launch(void* const* d_in, const int* in_sizes, int n_in,
                              void* d_out, int out_size) {
    const float* nf = (const float*)d_in[0];
    const float* ef = (const float*)d_in[1];
    const int*   src = (const int*)d_in[2];
    const int*   dst = (const int*)d_in[3];
    const float* Wq = (const float*)d_in[4];
    const float* bq = (const float*)d_in[5];
    const float* Wk = (const float*)d_in[6];
    const float* bk = (const float*)d_in[7];
    const float* Wv = (const float*)d_in[8];
    const float* bv = (const float*)d_in[9];
    const float* We = (const float*)d_in[10];
    const float* be = (const float*)d_in[11];

    int N = in_sizes[0] / 64;
    int E = in_sizes[2];

    float* h_out = (float*)d_out;                  // [N, 64]
    float* e_out = (float*)d_out + (size_t)N * 64; // [E, 64]

    const int NODE_SMEM = 2 * NTROWS * STR * 4;                  // 34816
    const int PROJ_SMEM = 2 * ETROWS * STR * 4 + 16384 + 2048;   // 53248
    cudaFuncSetAttribute(node_mma_kernel,
                         cudaFuncAttributeMaxDynamicSharedMemorySize, NODE_SMEM);
    cudaFuncSetAttribute(edge_proj_kernel,
                         cudaFuncAttributeMaxDynamicSharedMemorySize, PROJ_SMEM);

    // launch order: zero(0), node x3 (1,2,3), score(4), proj(5), scatter(6), fin(7)
    // -> ncu capture (absolute launch index 3) lands on a node chunk
    zero_acc_kernel<<<512, 256>>>(N);

    long third = (N + 2) / 3;
    for (int i = 0; i < 3; i++) {
        long off = (long)i * third;
        if (off >= N) break;
        long cnt = (N - off < third) ? (N - off) : third;
        int blocks = (int)((cnt + NTROWS * NPT - 1) / (NTROWS * NPT));
        node_mma_kernel<<<blocks, 256, NODE_SMEM>>>(nf, Wq, bq, Wk, bk, Wv, bv,
                                                    off, N);
    }

    int sblocks = (int)(((long)E * 8 + 255) / 256);
    score_kernel<<<sblocks, 256>>>(src, dst, E);

    {
        int blocks = (int)((E + ETROWS * EPT - 1) / (ETROWS * EPT));
        edge_proj_kernel<<<blocks, 256, PROJ_SMEM>>>(ef, We, be, e_out, E);
    }

    scatter_kernel<<<sblocks, 256>>>(src, dst, E);

    finalize_kernel<<<((N * 16) + 255) / 256, 256>>>(h_out, N);
}

// round 13
// speedup vs baseline: 1.2274x; 1.0344x over previous
#include <cuda_runtime.h>
#include <cuda_bf16.h>
#include <cstddef>

// Problem constants: N=100000, E=1000000, F=64, H=8, D=8
#define MAXN 100000
#define MAXE 1000000
#define CLIPV 5.0f
#define INV_SQRT_D 0.35355339059327373f
#define STR 68      // padded smem row stride (floats)
#define NTROWS 64   // node tile rows
#define NPT 4       // node tiles per block
#define ETROWS 64   // proj tile rows
#define EPT 8       // proj tiles per block

// ---------------- scratch (device globals) -----------------------------------
__device__ float g_Q[(size_t)MAXN * 64];
__device__ float g_K[(size_t)MAXN * 64];
__device__ float g_V[(size_t)MAXN * 64];
__device__ float g_acc[(size_t)MAXN * 72];  // 64 wV + 8 z per node
__device__ float g_sc[(size_t)MAXE * 8];    // per (edge,head) clipped score
__device__ float g_w[(size_t)MAXE * 8];     // per (edge,head) exp weight

// ---------------- helpers ----------------------------------------------------
__device__ __forceinline__ float clipf(float x) {
    return fminf(fmaxf(x, -CLIPV), CLIPV);
}
__device__ __forceinline__ void red4(float* p, float a, float b, float c, float d) {
    asm volatile("red.global.add.v4.f32 [%0], {%1, %2, %3, %4};"
                 :: "l"(p), "f"(a), "f"(b), "f"(c), "f"(d) : "memory");
}
__device__ __forceinline__ void split2(float x0, float x1, unsigned& hi, unsigned& lo) {
    __nv_bfloat16 h0 = __float2bfloat16_rn(x0);
    __nv_bfloat16 h1 = __float2bfloat16_rn(x1);
    float r0 = x0 - __bfloat162float(h0);
    float r1 = x1 - __bfloat162float(h1);
    __nv_bfloat162 H; H.x = h0; H.y = h1;
    __nv_bfloat162 L; L.x = __float2bfloat16_rn(r0); L.y = __float2bfloat16_rn(r1);
    hi = *reinterpret_cast<unsigned*>(&H);
    lo = *reinterpret_cast<unsigned*>(&L);
}
__device__ __forceinline__ void mma_bf16(float c[4], const unsigned a[4], const unsigned b[2]) {
    asm volatile(
        "mma.sync.aligned.m16n8k16.row.col.f32.bf16.bf16.f32 "
        "{%0,%1,%2,%3}, {%4,%5,%6,%7}, {%8,%9}, {%0,%1,%2,%3};"
        : "+f"(c[0]), "+f"(c[1]), "+f"(c[2]), "+f"(c[3])
        : "r"(a[0]), "r"(a[1]), "r"(a[2]), "r"(a[3]), "r"(b[0]), "r"(b[1]));
}
__device__ __forceinline__ void load_a_frags(const float* sT, int R, int lq, int lr,
                                             unsigned ah[4][4], unsigned al[4][4]) {
    #pragma unroll
    for (int k = 0; k < 4; k++) {
        const float* base = sT + (size_t)(R + lq) * STR + 16 * k + 2 * lr;
        float2 q0 = *reinterpret_cast<const float2*>(base);
        float2 q1 = *reinterpret_cast<const float2*>(base + 8 * STR);
        float2 q2 = *reinterpret_cast<const float2*>(base + 8);
        float2 q3 = *reinterpret_cast<const float2*>(base + 8 * STR + 8);
        split2(q0.x, q0.y, ah[k][0], al[k][0]);
        split2(q1.x, q1.y, ah[k][1], al[k][1]);
        split2(q2.x, q2.y, ah[k][2], al[k][2]);
        split2(q3.x, q3.y, ah[k][3], al[k][3]);
    }
}
__device__ __forceinline__ unsigned saddr(const void* p) {
    return (unsigned)__cvta_generic_to_shared(p);
}

// ---------------- kernel 0: zero g_acc ---------------------------------------
__global__ __launch_bounds__(256)
void zero_acc_kernel(int N) {
    float4 z4 = make_float4(0.f, 0.f, 0.f, 0.f);
    float4* ap = reinterpret_cast<float4*>(g_acc);
    long total4 = (long)N * 18;
    for (long i = (long)blockIdx.x * 256 + threadIdx.x; i < total4;
         i += (long)gridDim.x * 256)
        ap[i] = z4;
}

// ---------------- kernel 1: node projections (pipelined, B in regs) ----------
// 64-row tiles, NPT per block, cp.async double buffer. Warp w owns n-tiles
// {3w,3w+1,3w+2} of 24 (Q:0-7, K:8-15, V:16-23); B fragments in registers.
__global__ __launch_bounds__(256, 2)
void node_mma_kernel(const float* __restrict__ nf,
                     const float* __restrict__ Wq, const float* __restrict__ bq,
                     const float* __restrict__ Wk, const float* __restrict__ bk,
                     const float* __restrict__ Wv, const float* __restrict__ bv,
                     int N) {
    extern __shared__ float smemf[];
    float* bufs[2] = { smemf, smemf + NTROWS * STR };

    int tid = threadIdx.x;
    long base = (long)blockIdx.x * (NTROWS * NPT);

    int w = tid >> 5, l = tid & 31;
    int lq = l >> 2, lr = l & 3;

    unsigned bh[3][4][2], bl[3][4][2];
    float2 bb[3];
    #pragma unroll
    for (int t3 = 0; t3 < 3; t3++) {
        int g = 3 * w + t3;
        int which = g >> 3;
        const float* W = (which == 0) ? Wq : (which == 1) ? Wk : Wv;
        const float* bp = (which == 0) ? bq : (which == 1) ? bk : bv;
        int nrow = (g & 7) * 8 + lq;
        #pragma unroll
        for (int k = 0; k < 4; k++) {
            const float* wr = W + (size_t)nrow * 64 + 16 * k + 2 * lr;
            float2 a = __ldg(reinterpret_cast<const float2*>(wr));
            float2 b = __ldg(reinterpret_cast<const float2*>(wr + 8));
            split2(a.x, a.y, bh[t3][k][0], bl[t3][k][0]);
            split2(b.x, b.y, bh[t3][k][1], bl[t3][k][1]);
        }
        bb[t3] = __ldg(reinterpret_cast<const float2*>(bp + (g & 7) * 8 + 2 * lr));
    }

    auto load_tile = [&](int ti) {
        float* buf = bufs[ti & 1];
        long tBase = base + (long)ti * NTROWS;
        #pragma unroll
        for (int it = 0; it < 4; it++) {
            int i = it * 256 + tid;
            int r = i >> 4, c4 = i & 15;
            long n = tBase + r;
            if (n >= N) n = N - 1;
            const float* srcp = nf + n * 64 + 4 * c4;
            unsigned daddr = saddr(buf + (size_t)r * STR + 4 * c4);
            asm volatile("cp.async.cg.shared.global [%0], [%1], 16;"
                         :: "r"(daddr), "l"(srcp));
        }
        asm volatile("cp.async.commit_group;");
    };

    load_tile(0);
    load_tile(1);

    #pragma unroll 1
    for (int t = 0; t < NPT; t++) {
        float* buf = bufs[t & 1];
        long tBase = base + (long)t * NTROWS;

        if (t == NPT - 1) asm volatile("cp.async.wait_group 0;");
        else              asm volatile("cp.async.wait_group 1;");
        __syncthreads();

        #pragma unroll
        for (int mt = 0; mt < 4; mt++) {
            unsigned ah[4][4], al[4][4];
            load_a_frags(buf, 16 * mt, lq, lr, ah, al);
            if (mt == 3) {   // all warps done reading buf -> free for t+2
                __syncthreads();
                if (t + 2 < NPT) load_tile(t + 2);
            }
            long n0 = tBase + 16 * mt + lq;
            long n1 = n0 + 8;
            #pragma unroll
            for (int t3 = 0; t3 < 3; t3++) {
                int g = 3 * w + t3;
                int which = g >> 3;
                float* outp = (which == 0) ? g_Q : (which == 1) ? g_K : g_V;
                int colBase = 8 * (g & 7) + 2 * lr;
                float acc[4] = {0.f, 0.f, 0.f, 0.f};
                #pragma unroll
                for (int k = 0; k < 4; k++) {
                    mma_bf16(acc, ah[k], bh[t3][k]);
                    mma_bf16(acc, ah[k], bl[t3][k]);
                    mma_bf16(acc, al[k], bh[t3][k]);
                }
                if (n0 < N)
                    *reinterpret_cast<float2*>(outp + n0 * 64 + colBase) =
                        make_float2(acc[0] + bb[t3].x, acc[1] + bb[t3].y);
                if (n1 < N)
                    *reinterpret_cast<float2*>(outp + n1 * 64 + colBase) =
                        make_float2(acc[2] + bb[t3].x, acc[3] + bb[t3].y);
            }
        }
    }
}

// ---------------- kernel 2: scores sc[e][h] = clip(K[src].Q[dst]/sqrt(D)) ----
__global__ __launch_bounds__(256)
void score_kernel(const int* __restrict__ src, const int* __restrict__ dst,
                  int E) {
    long t = (long)blockIdx.x * 256 + threadIdx.x;
    long e = t >> 3;
    if (e >= E) return;
    int h = (int)(t & 7);

    int s = __ldg(src + e);
    int d = __ldg(dst + e);

    const float4* Kp = reinterpret_cast<const float4*>(g_K + (size_t)s * 64 + 8 * h);
    const float4* Qp = reinterpret_cast<const float4*>(g_Q + (size_t)d * 64 + 8 * h);
    float4 k0 = Kp[0], k1 = Kp[1];
    float4 q0 = Qp[0], q1 = Qp[1];

    float sc = k0.x * q0.x + k0.y * q0.y + k0.z * q0.z + k0.w * q0.w
             + k1.x * q1.x + k1.y * q1.y + k1.z * q1.z + k1.w * q1.w;
    g_sc[t] = clipf(sc * INV_SQRT_D);
}

// ---------------- kernel 3: pipelined edge projection GEMM (round-9 form) ----
// 64-row tiles, EPT per block, cp.async double buffer; B frags pre-split in
// 16KB smem; register-resident epilogue (e_out from accumulators, quad-shfl
// row sums); scores staged per tile via 2KB smem buffer.
__global__ __launch_bounds__(256, 3)
void edge_proj_kernel(const float* __restrict__ ef,
                      const float* __restrict__ We, const float* __restrict__ be,
                      float* __restrict__ e_out, int E) {
    extern __shared__ float smem[];
    float* bufs[2] = { smem, smem + ETROWS * STR };
    uint4* sB = reinterpret_cast<uint4*>(smem + 2 * ETROWS * STR);  // [8][4][32] 16KB
    float* sSc = reinterpret_cast<float*>(sB + 1024);               // [64][8] 2KB

    int tid = threadIdx.x;
    long base = (long)blockIdx.x * (ETROWS * EPT);

    for (int i = tid; i < 1024; i += 256) {
        int t = i >> 7, k = (i >> 5) & 3, l = i & 31;
        int lq = l >> 2, lr = l & 3;
        const float* wr = We + (size_t)(8 * t + lq) * 64 + 16 * k + 2 * lr;
        float w0 = __ldg(wr),     w1 = __ldg(wr + 1);
        float w8 = __ldg(wr + 8), w9 = __ldg(wr + 9);
        unsigned h0, l0, h1, l1;
        split2(w0, w1, h0, l0);
        split2(w8, w9, h1, l1);
        sB[i] = make_uint4(h0, h1, l0, l1);
    }

    auto load_tile = [&](float* buf, long tBase) {
        for (int i = tid; i < ETROWS * 16; i += 256) {
            int r = i >> 4, c4 = i & 15;
            long e = tBase + r;
            if (e >= E) e = E - 1;
            const float* srcp = ef + e * 64 + 4 * c4;
            unsigned daddr = saddr(buf + (size_t)r * STR + 4 * c4);
            asm volatile("cp.async.cg.shared.global [%0], [%1], 16;"
                         :: "r"(daddr), "l"(srcp));
        }
        asm volatile("cp.async.commit_group;");
    };

    load_tile(bufs[0], base);
    load_tile(bufs[1], base + ETROWS);

    int w = tid >> 5, l = tid & 31;
    int lq = l >> 2, lr = l & 3;
    int mt = w >> 1;        // m-tile 0..3
    int nh = w & 1;         // n-half: heads 4*nh..4*nh+3
    int R = 16 * mt;

    float2 bb[4];
    #pragma unroll
    for (int tt = 0; tt < 4; tt++)
        bb[tt] = __ldg(reinterpret_cast<const float2*>(be + 8 * (4 * nh + tt) + 2 * lr));

    #pragma unroll 1
    for (int t = 0; t < EPT; t++) {
        float* buf = bufs[t & 1];
        long tBase = base + (long)t * ETROWS;

        if (t == EPT - 1) asm volatile("cp.async.wait_group 0;");
        else              asm volatile("cp.async.wait_group 1;");
        __syncthreads();

        if (tid < 128) {
            long e4 = tBase + (tid >> 1);
            if (e4 < E)
                reinterpret_cast<float4*>(sSc)[tid] =
                    __ldg(reinterpret_cast<const float4*>(g_sc) + tBase * 2 + tid);
        }

        unsigned ah[4][4], al[4][4];
        load_a_frags(buf, R, lq, lr, ah, al);
        __syncthreads();

        if (t + 2 < EPT) load_tile(buf, tBase + 2 * ETROWS);

        long e0 = tBase + R + lq;
        long e1 = e0 + 8;

        #pragma unroll
        for (int tt = 0; tt < 4; tt++) {
            int tn = 4 * nh + tt;
            float acc[4] = {0.f, 0.f, 0.f, 0.f};
            #pragma unroll
            for (int k = 0; k < 4; k++) {
                uint4 b = sB[(tn * 4 + k) * 32 + l];
                unsigned bhv[2] = { b.x, b.y };
                unsigned blv[2] = { b.z, b.w };
                mma_bf16(acc, ah[k], bhv);
                mma_bf16(acc, ah[k], blv);
                mma_bf16(acc, al[k], bhv);
            }
            float p0 = acc[0] + bb[tt].x, p1 = acc[1] + bb[tt].y;
            float p2 = acc[2] + bb[tt].x, p3 = acc[3] + bb[tt].y;
            float ps0 = p0 + p1, ps1 = p2 + p3;
            ps0 += __shfl_xor_sync(0xffffffffu, ps0, 1);
            ps0 += __shfl_xor_sync(0xffffffffu, ps0, 2);
            ps1 += __shfl_xor_sync(0xffffffffu, ps1, 1);
            ps1 += __shfl_xor_sync(0xffffffffu, ps1, 2);
            float sc0 = sSc[(R + lq) * 8 + tn];
            float sc1 = sSc[(R + 8 + lq) * 8 + tn];
            int colBase = 8 * tn + 2 * lr;
            if (e0 < E) {
                __stcs(reinterpret_cast<float2*>(e_out + e0 * 64 + colBase),
                       make_float2(sc0 * p0, sc0 * p1));
                if (lr == 0) g_w[e0 * 8 + tn] = __expf(clipf(sc0 * ps0));
            }
            if (e1 < E) {
                __stcs(reinterpret_cast<float2*>(e_out + e1 * 64 + colBase),
                       make_float2(sc1 * p2, sc1 * p3));
                if (lr == 0) g_w[e1 * 8 + tn] = __expf(clipf(sc1 * ps1));
            }
        }
    }
}

// ---------------- kernel 4: scatter wV and z into g_acc ----------------------
__global__ __launch_bounds__(256)
void scatter_kernel(const int* __restrict__ src, const int* __restrict__ dst,
                    int E) {
    long t = (long)blockIdx.x * 256 + threadIdx.x;
    long e = t >> 3;
    int h = (int)(t & 7);
    bool valid = e < E;
    long ec = valid ? e : (long)E - 1;

    int s = __ldg(src + ec);
    int d = __ldg(dst + ec);
    float wv = __ldg(g_w + ec * 8 + h);

    const float4* Vp = reinterpret_cast<const float4*>(g_V + (size_t)s * 64 + 8 * h);
    float4 v0 = Vp[0], v1 = Vp[1];

    float w1 = __shfl_down_sync(0xffffffffu, wv, 1);
    float w2 = __shfl_down_sync(0xffffffffu, wv, 2);
    float w3 = __shfl_down_sync(0xffffffffu, wv, 3);

    if (valid) {
        float* ap = g_acc + (size_t)d * 72 + 8 * h;
        red4(ap,     v0.x * wv, v0.y * wv, v0.z * wv, v0.w * wv);
        red4(ap + 4, v1.x * wv, v1.y * wv, v1.z * wv, v1.w * wv);
        if ((h & 3) == 0)
            red4(g_acc + (size_t)d * 72 + 64 + h, wv, w1, w2, w3);
    }
}

// ---------------- kernel 5: finalize h_out = wV / (z + 1e-6) -----------------
__global__ __launch_bounds__(256)
void finalize_kernel(float* __restrict__ h_out, int N) {
    int t = blockIdx.x * 256 + threadIdx.x;
    if (t >= N * 16) return;
    int n = t >> 4, g = t & 15;
    const float* ap = g_acc + (size_t)n * 72;
    float4 wv = *reinterpret_cast<const float4*>(ap + 4 * g);
    float z = ap[64 + (g >> 1)];
    float inv = 1.0f / (z + 1e-6f);
    float4 r;
    r.x = wv.x * inv; r.y = wv.y * inv; r.z = wv.z * inv; r.w = wv.w * inv;
    __stcs(reinterpret_cast<float4*>(h_out + (size_t)n * 64 + 4 * g), r);
}

// ---------------- launch ------------------------------------------------------
extern "C" void kernel_launch(void* const* d_in, const int* in_sizes, int n_in,
                              void* d_out, int out_size) {
    const float* nf = (const float*)d_in[0];
    const float* ef = (const float*)d_in[1];
    const int*   src = (const int*)d_in[2];
    const int*   dst = (const int*)d_in[3];
    const float* Wq = (const float*)d_in[4];
    const float* bq = (const float*)d_in[5];
    const float* Wk = (const float*)d_in[6];
    const float* bk = (const float*)d_in[7];
    const float* Wv = (const float*)d_in[8];
    const float* bv = (const float*)d_in[9];
    const float* We = (const float*)d_in[10];
    const float* be = (const float*)d_in[11];

    int N = in_sizes[0] / 64;
    int E = in_sizes[2];

    float* h_out = (float*)d_out;                  // [N, 64]
    float* e_out = (float*)d_out + (size_t)N * 64; // [E, 64]

    const int NODE_SMEM = 2 * NTROWS * STR * 4;                  // 34816
    const int PROJ_SMEM = 2 * ETROWS * STR * 4 + 16384 + 2048;   // 53248
    cudaFuncSetAttribute(node_mma_kernel,
                         cudaFuncAttributeMaxDynamicSharedMemorySize, NODE_SMEM);
    cudaFuncSetAttribute(edge_proj_kernel,
                         cudaFuncAttributeMaxDynamicSharedMemorySize, PROJ_SMEM);

    // launch order: zero(0), node(1), score(2), proj(3), scatter(4), fin(5)
    // -> ncu capture (absolute launch index 3) lands on edge_proj_kernel
    zero_acc_kernel<<<512, 256>>>(N);

    {
        int blocks = (N + NTROWS * NPT - 1) / (NTROWS * NPT);
        node_mma_kernel<<<blocks, 256, NODE_SMEM>>>(nf, Wq, bq, Wk, bk, Wv, bv, N);
    }

    int sblocks = (int)(((long)E * 8 + 255) / 256);
    score_kernel<<<sblocks, 256>>>(src, dst, E);

    {
        int blocks = (int)((E + ETROWS * EPT - 1) / (ETROWS * EPT));
        edge_proj_kernel<<<blocks, 256, PROJ_SMEM>>>(ef, We, be, e_out, E);
    }

    scatter_kernel<<<sblocks, 256>>>(src, dst, E);

    finalize_kernel<<<((N * 16) + 255) / 256, 256>>>(h_out, N);
}

// round 14
// speedup vs baseline: 1.2552x; 1.0227x over previous
#include <cuda_runtime.h>
#include <cuda_bf16.h>
#include <cstddef>

// Problem constants: N=100000, E=1000000, F=64, H=8, D=8
#define MAXN 100000
#define MAXE 1000000
#define CLIPV 5.0f
#define INV_SQRT_D 0.35355339059327373f
#define STR 68      // padded smem row stride (floats)
#define NTROWS 64   // node tile rows
#define NPT 4       // node tiles per block
#define ETROWS 64   // proj tile rows
#define EPT 8       // proj tiles per block

// ---------------- scratch (device globals) -----------------------------------
__device__ float g_Q[(size_t)MAXN * 64];
__device__ float g_K[(size_t)MAXN * 64];
__device__ float g_V[(size_t)MAXN * 64];
__device__ float g_acc[(size_t)MAXN * 72];  // 64 wV + 8 z per node
__device__ float g_sc[(size_t)MAXE * 8];    // per (edge,head) clipped score
__device__ float g_w[(size_t)MAXE * 8];     // per (edge,head) exp weight

// ---------------- helpers ----------------------------------------------------
__device__ __forceinline__ float clipf(float x) {
    return fminf(fmaxf(x, -CLIPV), CLIPV);
}
__device__ __forceinline__ void red4(float* p, float a, float b, float c, float d) {
    asm volatile("red.global.add.v4.f32 [%0], {%1, %2, %3, %4};"
                 :: "l"(p), "f"(a), "f"(b), "f"(c), "f"(d) : "memory");
}
__device__ __forceinline__ void split2(float x0, float x1, unsigned& hi, unsigned& lo) {
    __nv_bfloat16 h0 = __float2bfloat16_rn(x0);
    __nv_bfloat16 h1 = __float2bfloat16_rn(x1);
    float r0 = x0 - __bfloat162float(h0);
    float r1 = x1 - __bfloat162float(h1);
    __nv_bfloat162 H; H.x = h0; H.y = h1;
    __nv_bfloat162 L; L.x = __float2bfloat16_rn(r0); L.y = __float2bfloat16_rn(r1);
    hi = *reinterpret_cast<unsigned*>(&H);
    lo = *reinterpret_cast<unsigned*>(&L);
}
__device__ __forceinline__ void mma_bf16(float c[4], const unsigned a[4], const unsigned b[2]) {
    asm volatile(
        "mma.sync.aligned.m16n8k16.row.col.f32.bf16.bf16.f32 "
        "{%0,%1,%2,%3}, {%4,%5,%6,%7}, {%8,%9}, {%0,%1,%2,%3};"
        : "+f"(c[0]), "+f"(c[1]), "+f"(c[2]), "+f"(c[3])
        : "r"(a[0]), "r"(a[1]), "r"(a[2]), "r"(a[3]), "r"(b[0]), "r"(b[1]));
}
__device__ __forceinline__ void load_a_frags(const float* sT, int R, int lq, int lr,
                                             unsigned ah[4][4], unsigned al[4][4]) {
    #pragma unroll
    for (int k = 0; k < 4; k++) {
        const float* base = sT + (size_t)(R + lq) * STR + 16 * k + 2 * lr;
        float2 q0 = *reinterpret_cast<const float2*>(base);
        float2 q1 = *reinterpret_cast<const float2*>(base + 8 * STR);
        float2 q2 = *reinterpret_cast<const float2*>(base + 8);
        float2 q3 = *reinterpret_cast<const float2*>(base + 8 * STR + 8);
        split2(q0.x, q0.y, ah[k][0], al[k][0]);
        split2(q1.x, q1.y, ah[k][1], al[k][1]);
        split2(q2.x, q2.y, ah[k][2], al[k][2]);
        split2(q3.x, q3.y, ah[k][3], al[k][3]);
    }
}
__device__ __forceinline__ unsigned saddr(const void* p) {
    return (unsigned)__cvta_generic_to_shared(p);
}

// ---------------- kernel 1: node projections (pipelined, B in regs) + zero ---
__global__ __launch_bounds__(256, 2)
void node_mma_kernel(const float* __restrict__ nf,
                     const float* __restrict__ Wq, const float* __restrict__ bq,
                     const float* __restrict__ Wk, const float* __restrict__ bk,
                     const float* __restrict__ Wv, const float* __restrict__ bv,
                     int N) {
    extern __shared__ float smemf[];
    float* bufs[2] = { smemf, smemf + NTROWS * STR };

    int tid = threadIdx.x;
    long base = (long)blockIdx.x * (NTROWS * NPT);

    // zero g_acc (grid-stride, vectorized)
    {
        float4 z4 = make_float4(0.f, 0.f, 0.f, 0.f);
        float4* ap = reinterpret_cast<float4*>(g_acc);
        long total4 = (long)N * 18;
        for (long i = (long)blockIdx.x * 256 + tid; i < total4; i += (long)gridDim.x * 256)
            ap[i] = z4;
    }

    int w = tid >> 5, l = tid & 31;
    int lq = l >> 2, lr = l & 3;

    unsigned bh[3][4][2], bl[3][4][2];
    float2 bb[3];
    #pragma unroll
    for (int t3 = 0; t3 < 3; t3++) {
        int g = 3 * w + t3;
        int which = g >> 3;
        const float* W = (which == 0) ? Wq : (which == 1) ? Wk : Wv;
        const float* bp = (which == 0) ? bq : (which == 1) ? bk : bv;
        int nrow = (g & 7) * 8 + lq;
        #pragma unroll
        for (int k = 0; k < 4; k++) {
            const float* wr = W + (size_t)nrow * 64 + 16 * k + 2 * lr;
            float2 a = __ldg(reinterpret_cast<const float2*>(wr));
            float2 b = __ldg(reinterpret_cast<const float2*>(wr + 8));
            split2(a.x, a.y, bh[t3][k][0], bl[t3][k][0]);
            split2(b.x, b.y, bh[t3][k][1], bl[t3][k][1]);
        }
        bb[t3] = __ldg(reinterpret_cast<const float2*>(bp + (g & 7) * 8 + 2 * lr));
    }

    auto load_tile = [&](int ti) {
        float* buf = bufs[ti & 1];
        long tBase = base + (long)ti * NTROWS;
        #pragma unroll
        for (int it = 0; it < 4; it++) {
            int i = it * 256 + tid;
            int r = i >> 4, c4 = i & 15;
            long n = tBase + r;
            if (n >= N) n = N - 1;
            const float* srcp = nf + n * 64 + 4 * c4;
            unsigned daddr = saddr(buf + (size_t)r * STR + 4 * c4);
            asm volatile("cp.async.cg.shared.global [%0], [%1], 16;"
                         :: "r"(daddr), "l"(srcp));
        }
        asm volatile("cp.async.commit_group;");
    };

    load_tile(0);
    load_tile(1);

    #pragma unroll 1
    for (int t = 0; t < NPT; t++) {
        float* buf = bufs[t & 1];
        long tBase = base + (long)t * NTROWS;

        if (t == NPT - 1) asm volatile("cp.async.wait_group 0;");
        else              asm volatile("cp.async.wait_group 1;");
        __syncthreads();

        #pragma unroll
        for (int mt = 0; mt < 4; mt++) {
            unsigned ah[4][4], al[4][4];
            load_a_frags(buf, 16 * mt, lq, lr, ah, al);
            if (mt == 3) {   // all warps done reading buf -> free for t+2
                __syncthreads();
                if (t + 2 < NPT) load_tile(t + 2);
            }
            long n0 = tBase + 16 * mt + lq;
            long n1 = n0 + 8;
            #pragma unroll
            for (int t3 = 0; t3 < 3; t3++) {
                int g = 3 * w + t3;
                int which = g >> 3;
                float* outp = (which == 0) ? g_Q : (which == 1) ? g_K : g_V;
                int colBase = 8 * (g & 7) + 2 * lr;
                float acc[4] = {0.f, 0.f, 0.f, 0.f};
                #pragma unroll
                for (int k = 0; k < 4; k++) {
                    mma_bf16(acc, ah[k], bh[t3][k]);
                    mma_bf16(acc, ah[k], bl[t3][k]);
                    mma_bf16(acc, al[k], bh[t3][k]);
                }
                if (n0 < N)
                    *reinterpret_cast<float2*>(outp + n0 * 64 + colBase) =
                        make_float2(acc[0] + bb[t3].x, acc[1] + bb[t3].y);
                if (n1 < N)
                    *reinterpret_cast<float2*>(outp + n1 * 64 + colBase) =
                        make_float2(acc[2] + bb[t3].x, acc[3] + bb[t3].y);
            }
        }
    }
}

// ---------------- kernel 2: scores, 2-way MLP batched ------------------------
// thread handles units u and u+4E (edges e and e+E/2): 8 independent LDG.128
// in flight; g_sc stores coalesced for both halves.
__global__ __launch_bounds__(256)
void score_kernel(const int* __restrict__ src, const int* __restrict__ dst,
                  int E) {
    long HALF = (long)E * 4;
    long u = (long)blockIdx.x * 256 + threadIdx.x;
    if (u >= HALF) return;
    long u1 = u + HALF;
    long e0 = u >> 3,  e1 = u1 >> 3;
    int  h0 = (int)(u & 7), h1 = (int)(u1 & 7);

    int s0 = __ldg(src + e0), d0 = __ldg(dst + e0);
    int s1 = __ldg(src + e1), d1 = __ldg(dst + e1);

    const float4* K0 = reinterpret_cast<const float4*>(g_K + (size_t)s0 * 64 + 8 * h0);
    const float4* Q0 = reinterpret_cast<const float4*>(g_Q + (size_t)d0 * 64 + 8 * h0);
    const float4* K1 = reinterpret_cast<const float4*>(g_K + (size_t)s1 * 64 + 8 * h1);
    const float4* Q1 = reinterpret_cast<const float4*>(g_Q + (size_t)d1 * 64 + 8 * h1);
    float4 ka0 = K0[0], ka1 = K0[1], qa0 = Q0[0], qa1 = Q0[1];
    float4 kb0 = K1[0], kb1 = K1[1], qb0 = Q1[0], qb1 = Q1[1];

    float sc0 = ka0.x * qa0.x + ka0.y * qa0.y + ka0.z * qa0.z + ka0.w * qa0.w
              + ka1.x * qa1.x + ka1.y * qa1.y + ka1.z * qa1.z + ka1.w * qa1.w;
    float sc1 = kb0.x * qb0.x + kb0.y * qb0.y + kb0.z * qb0.z + kb0.w * qb0.w
              + kb1.x * qb1.x + kb1.y * qb1.y + kb1.z * qb1.z + kb1.w * qb1.w;

    g_sc[u]  = clipf(sc0 * INV_SQRT_D);
    g_sc[u1] = clipf(sc1 * INV_SQRT_D);
}

// ---------------- kernel 3: pipelined edge projection GEMM (round-9 form) ----
__global__ __launch_bounds__(256, 3)
void edge_proj_kernel(const float* __restrict__ ef,
                      const float* __restrict__ We, const float* __restrict__ be,
                      float* __restrict__ e_out, int E) {
    extern __shared__ float smem[];
    float* bufs[2] = { smem, smem + ETROWS * STR };
    uint4* sB = reinterpret_cast<uint4*>(smem + 2 * ETROWS * STR);  // [8][4][32] 16KB
    float* sSc = reinterpret_cast<float*>(sB + 1024);               // [64][8] 2KB

    int tid = threadIdx.x;
    long base = (long)blockIdx.x * (ETROWS * EPT);

    for (int i = tid; i < 1024; i += 256) {
        int t = i >> 7, k = (i >> 5) & 3, l = i & 31;
        int lq = l >> 2, lr = l & 3;
        const float* wr = We + (size_t)(8 * t + lq) * 64 + 16 * k + 2 * lr;
        float w0 = __ldg(wr),     w1 = __ldg(wr + 1);
        float w8 = __ldg(wr + 8), w9 = __ldg(wr + 9);
        unsigned h0, l0, h1, l1;
        split2(w0, w1, h0, l0);
        split2(w8, w9, h1, l1);
        sB[i] = make_uint4(h0, h1, l0, l1);
    }

    auto load_tile = [&](float* buf, long tBase) {
        for (int i = tid; i < ETROWS * 16; i += 256) {
            int r = i >> 4, c4 = i & 15;
            long e = tBase + r;
            if (e >= E) e = E - 1;
            const float* srcp = ef + e * 64 + 4 * c4;
            unsigned daddr = saddr(buf + (size_t)r * STR + 4 * c4);
            asm volatile("cp.async.cg.shared.global [%0], [%1], 16;"
                         :: "r"(daddr), "l"(srcp));
        }
        asm volatile("cp.async.commit_group;");
    };

    load_tile(bufs[0], base);
    load_tile(bufs[1], base + ETROWS);

    int w = tid >> 5, l = tid & 31;
    int lq = l >> 2, lr = l & 3;
    int mt = w >> 1;
    int nh = w & 1;
    int R = 16 * mt;

    float2 bb[4];
    #pragma unroll
    for (int tt = 0; tt < 4; tt++)
        bb[tt] = __ldg(reinterpret_cast<const float2*>(be + 8 * (4 * nh + tt) + 2 * lr));

    #pragma unroll 1
    for (int t = 0; t < EPT; t++) {
        float* buf = bufs[t & 1];
        long tBase = base + (long)t * ETROWS;

        if (t == EPT - 1) asm volatile("cp.async.wait_group 0;");
        else              asm volatile("cp.async.wait_group 1;");
        __syncthreads();

        if (tid < 128) {
            long e4 = tBase + (tid >> 1);
            if (e4 < E)
                reinterpret_cast<float4*>(sSc)[tid] =
                    __ldg(reinterpret_cast<const float4*>(g_sc) + tBase * 2 + tid);
        }

        unsigned ah[4][4], al[4][4];
        load_a_frags(buf, R, lq, lr, ah, al);
        __syncthreads();

        if (t + 2 < EPT) load_tile(buf, tBase + 2 * ETROWS);

        long e0 = tBase + R + lq;
        long e1 = e0 + 8;

        #pragma unroll
        for (int tt = 0; tt < 4; tt++) {
            int tn = 4 * nh + tt;
            float acc[4] = {0.f, 0.f, 0.f, 0.f};
            #pragma unroll
            for (int k = 0; k < 4; k++) {
                uint4 b = sB[(tn * 4 + k) * 32 + l];
                unsigned bhv[2] = { b.x, b.y };
                unsigned blv[2] = { b.z, b.w };
                mma_bf16(acc, ah[k], bhv);
                mma_bf16(acc, ah[k], blv);
                mma_bf16(acc, al[k], bhv);
            }
            float p0 = acc[0] + bb[tt].x, p1 = acc[1] + bb[tt].y;
            float p2 = acc[2] + bb[tt].x, p3 = acc[3] + bb[tt].y;
            float ps0 = p0 + p1, ps1 = p2 + p3;
            ps0 += __shfl_xor_sync(0xffffffffu, ps0, 1);
            ps0 += __shfl_xor_sync(0xffffffffu, ps0, 2);
            ps1 += __shfl_xor_sync(0xffffffffu, ps1, 1);
            ps1 += __shfl_xor_sync(0xffffffffu, ps1, 2);
            float sc0 = sSc[(R + lq) * 8 + tn];
            float sc1 = sSc[(R + 8 + lq) * 8 + tn];
            int colBase = 8 * tn + 2 * lr;
            if (e0 < E) {
                __stcs(reinterpret_cast<float2*>(e_out + e0 * 64 + colBase),
                       make_float2(sc0 * p0, sc0 * p1));
                if (lr == 0) g_w[e0 * 8 + tn] = __expf(clipf(sc0 * ps0));
            }
            if (e1 < E) {
                __stcs(reinterpret_cast<float2*>(e_out + e1 * 64 + colBase),
                       make_float2(sc1 * p2, sc1 * p3));
                if (lr == 0) g_w[e1 * 8 + tn] = __expf(clipf(sc1 * ps1));
            }
        }
    }
}

// ---------------- kernel 4: scatter, 2-way MLP batched -----------------------
// thread handles units u and u+4E; z adds aggregated per quad via shfl.
__global__ __launch_bounds__(256)
void scatter_kernel(const int* __restrict__ src, const int* __restrict__ dst,
                    int E) {
    long HALF = (long)E * 4;
    long u = (long)blockIdx.x * 256 + threadIdx.x;
    bool valid = u < HALF;
    long uc = valid ? u : HALF - 1;
    long u1 = uc + HALF;
    long e0 = uc >> 3,  e1 = u1 >> 3;
    int  h0 = (int)(uc & 7), h1 = (int)(u1 & 7);

    int s0 = __ldg(src + e0), d0 = __ldg(dst + e0);
    int s1 = __ldg(src + e1), d1 = __ldg(dst + e1);
    float wv0 = __ldg(g_w + uc);
    float wv1 = __ldg(g_w + u1);

    const float4* V0 = reinterpret_cast<const float4*>(g_V + (size_t)s0 * 64 + 8 * h0);
    const float4* V1 = reinterpret_cast<const float4*>(g_V + (size_t)s1 * 64 + 8 * h1);
    float4 va0 = V0[0], va1 = V0[1];
    float4 vb0 = V1[0], vb1 = V1[1];

    // quad aggregation for z (HALF is a multiple of 4 -> quads never straddle)
    float a1 = __shfl_down_sync(0xffffffffu, wv0, 1);
    float a2 = __shfl_down_sync(0xffffffffu, wv0, 2);
    float a3 = __shfl_down_sync(0xffffffffu, wv0, 3);
    float b1 = __shfl_down_sync(0xffffffffu, wv1, 1);
    float b2 = __shfl_down_sync(0xffffffffu, wv1, 2);
    float b3 = __shfl_down_sync(0xffffffffu, wv1, 3);

    if (valid) {
        float* ap0 = g_acc + (size_t)d0 * 72 + 8 * h0;
        red4(ap0,     va0.x * wv0, va0.y * wv0, va0.z * wv0, va0.w * wv0);
        red4(ap0 + 4, va1.x * wv0, va1.y * wv0, va1.z * wv0, va1.w * wv0);
        if ((h0 & 3) == 0)
            red4(g_acc + (size_t)d0 * 72 + 64 + h0, wv0, a1, a2, a3);

        float* ap1 = g_acc + (size_t)d1 * 72 + 8 * h1;
        red4(ap1,     vb0.x * wv1, vb0.y * wv1, vb0.z * wv1, vb0.w * wv1);
        red4(ap1 + 4, vb1.x * wv1, vb1.y * wv1, vb1.z * wv1, vb1.w * wv1);
        if ((h1 & 3) == 0)
            red4(g_acc + (size_t)d1 * 72 + 64 + h1, wv1, b1, b2, b3);
    }
}

// ---------------- kernel 5: finalize h_out = wV / (z + 1e-6) -----------------
__global__ __launch_bounds__(256)
void finalize_kernel(float* __restrict__ h_out, int N) {
    int t = blockIdx.x * 256 + threadIdx.x;
    if (t >= N * 16) return;
    int n = t >> 4, g = t & 15;
    const float* ap = g_acc + (size_t)n * 72;
    float4 wv = *reinterpret_cast<const float4*>(ap + 4 * g);
    float z = ap[64 + (g >> 1)];
    float inv = 1.0f / (z + 1e-6f);
    float4 r;
    r.x = wv.x * inv; r.y = wv.y * inv; r.z = wv.z * inv; r.w = wv.w * inv;
    __stcs(reinterpret_cast<float4*>(h_out + (size_t)n * 64 + 4 * g), r);
}

// ---------------- launch ------------------------------------------------------
extern "C" void kernel_launch(void* const* d_in, const int* in_sizes, int n_in,
                              void* d_out, int out_size) {
    const float* nf = (const float*)d_in[0];
    const float* ef = (const float*)d_in[1];
    const int*   src = (const int*)d_in[2];
    const int*   dst = (const int*)d_in[3];
    const float* Wq = (const float*)d_in[4];
    const float* bq = (const float*)d_in[5];
    const float* Wk = (const float*)d_in[6];
    const float* bk = (const float*)d_in[7];
    const float* Wv = (const float*)d_in[8];
    const float* bv = (const float*)d_in[9];
    const float* We = (const float*)d_in[10];
    const float* be = (const float*)d_in[11];

    int N = in_sizes[0] / 64;
    int E = in_sizes[2];

    float* h_out = (float*)d_out;                  // [N, 64]
    float* e_out = (float*)d_out + (size_t)N * 64; // [E, 64]

    const int NODE_SMEM = 2 * NTROWS * STR * 4;                  // 34816
    const int PROJ_SMEM = 2 * ETROWS * STR * 4 + 16384 + 2048;   // 53248
    cudaFuncSetAttribute(node_mma_kernel,
                         cudaFuncAttributeMaxDynamicSharedMemorySize, NODE_SMEM);
    cudaFuncSetAttribute(edge_proj_kernel,
                         cudaFuncAttributeMaxDynamicSharedMemorySize, PROJ_SMEM);

    // launch order: node(0), score(1), proj(2), scatter(3), fin(4)
    // -> ncu capture (absolute launch index 3) lands on scatter_kernel
    {
        int blocks = (N + NTROWS * NPT - 1) / (NTROWS * NPT);
        node_mma_kernel<<<blocks, 256, NODE_SMEM>>>(nf, Wq, bq, Wk, bk, Wv, bv, N);
    }

    int hblocks = (int)(((long)E * 4 + 255) / 256);
    score_kernel<<<hblocks, 256>>>(src, dst, E);

    {
        int blocks = (int)((E + ETROWS * EPT - 1) / (ETROWS * EPT));
        edge_proj_kernel<<<blocks, 256, PROJ_SMEM>>>(ef, We, be, e_out, E);
    }

    scatter_kernel<<<hblocks, 256>>>(src, dst, E);

    finalize_kernel<<<((N * 16) + 255) / 256, 256>>>(h_out, N);
}